// round 1
// baseline (speedup 1.0000x reference)
#include <cuda_runtime.h>

// SSIM fused kernel for GB300.
// Input: img1, img2 : (16, 3, 512, 512) fp32. Only channel 0 used,
// cropped [4:508, 4:508] -> 504x504. 11x11 box filter, zero padding 5.
// Output: scalar fp32 mean of SSIM map.

#define IMG_H 512
#define IMG_W 512
#define CROP 4
#define OH 504
#define OW 504
#define NB 16
#define KS 11
#define KHALF 5

#define ROWS_PER_STRIP 56
#define NSTRIPS 9           // 9 * 56 = 504
#define THREADS 256
#define NCOLT 252           // threads 0..251 each own 2 output columns

__device__ double g_ssim_acc;

__global__ void ssim_init_kernel() {
    g_ssim_acc = 0.0;
}

__global__ void ssim_final_kernel(float* out) {
    out[0] = (float)(g_ssim_acc / (double)((double)NB * OH * OW));
}

// Ingest one input row: stage into smem (zero-padded), compute the five
// horizontal 11-wide window sums for this thread's 2 columns, push into the
// ring at `slot`, and add into the vertical running sums.
__device__ __forceinline__ void ingest_row(
    const float* __restrict__ base1, const float* __restrict__ base2,
    int irow,                // cropped row index, may be out of [0, OH)
    int c,                   // first of the 2 columns this thread owns
    bool active,
    float (&h)[5][11][2],
    float (&vs)[5][2],
    float* s1, float* s2,
    int t, int slot)
{
    float ha0, hb0, haa0, hbb0, hab0;
    float ha1, hb1, haa1, hbb1, hab1;
    ha0 = hb0 = haa0 = hbb0 = hab0 = 0.0f;
    ha1 = hb1 = haa1 = hbb1 = hab1 = 0.0f;

    if (irow >= 0 && irow < OH) {
        // protect previous iteration's smem readers
        __syncthreads();
        const float* r1 = base1 + (size_t)(irow + CROP) * IMG_W;
        const float* r2 = base2 + (size_t)(irow + CROP) * IMG_W;
        // smem index j corresponds to cropped col (j - 5); valid j in [5, 509)
        // global col = (j - 5) + CROP = j - 1
        #pragma unroll
        for (int j = t; j < OW + 2 * KHALF; j += THREADS) {
            bool v = (j >= KHALF) && (j < OW + KHALF);
            s1[j] = v ? r1[j - 1] : 0.0f;
            s2[j] = v ? r2[j - 1] : 0.0f;
        }
        __syncthreads();

        if (active) {
            // need s[c .. c+11] (12 values) per image; c is even -> float2 loads
            float a[12], b[12];
            const float2* p1 = reinterpret_cast<const float2*>(s1 + c);
            const float2* p2 = reinterpret_cast<const float2*>(s2 + c);
            #pragma unroll
            for (int i = 0; i < 6; i++) {
                float2 va = p1[i];
                float2 vb = p2[i];
                a[2 * i] = va.x; a[2 * i + 1] = va.y;
                b[2 * i] = vb.x; b[2 * i + 1] = vb.y;
            }
            // full window for col 0: positions 0..10
            #pragma unroll
            for (int j = 0; j < KS; j++) {
                ha0 += a[j];
                hb0 += b[j];
                haa0 = fmaf(a[j], a[j], haa0);
                hbb0 = fmaf(b[j], b[j], hbb0);
                hab0 = fmaf(a[j], b[j], hab0);
            }
            // incremental for col 1: drop pos 0, add pos 11
            ha1 = ha0 - a[0] + a[11];
            hb1 = hb0 - b[0] + b[11];
            haa1 = fmaf(a[11], a[11], fmaf(a[0], -a[0], haa0));
            hbb1 = fmaf(b[11], b[11], fmaf(b[0], -b[0], hbb0));
            hab1 = fmaf(a[11], b[11], fmaf(a[0], -b[0], hab0));
        }
    }

    h[0][slot][0] = ha0;  h[0][slot][1] = ha1;
    h[1][slot][0] = hb0;  h[1][slot][1] = hb1;
    h[2][slot][0] = haa0; h[2][slot][1] = haa1;
    h[3][slot][0] = hbb0; h[3][slot][1] = hbb1;
    h[4][slot][0] = hab0; h[4][slot][1] = hab1;

    vs[0][0] += ha0;  vs[0][1] += ha1;
    vs[1][0] += hb0;  vs[1][1] += hb1;
    vs[2][0] += haa0; vs[2][1] += haa1;
    vs[3][0] += hbb0; vs[3][1] += hbb1;
    vs[4][0] += hab0; vs[4][1] += hab1;
}

__device__ __forceinline__ float ssim_val(float S1, float S2, float Saa,
                                          float Sbb, float Sab)
{
    const float inv = 1.0f / 121.0f;
    const float C1 = 6.5025f;    // (0.01*255)^2
    const float C2 = 58.5225f;   // (0.03*255)^2
    float m1 = S1 * inv;
    float m2 = S2 * inv;
    float m11 = m1 * m1;
    float m22 = m2 * m2;
    float m12 = m1 * m2;
    float s11 = fmaf(Saa, inv, -m11);
    float s22 = fmaf(Sbb, inv, -m22);
    float s12 = fmaf(Sab, inv, -m12);
    float num = fmaf(2.0f, m12, C1) * fmaf(2.0f, s12, C2);
    float den = (m11 + m22 + C1) * (s11 + s22 + C2);
    return __fdividef(num, den);
}

__global__ __launch_bounds__(THREADS, 1)
void ssim_main_kernel(const float* __restrict__ img1,
                      const float* __restrict__ img2)
{
    __shared__ __align__(16) float s1[OW + 2 * KHALF + 6];
    __shared__ __align__(16) float s2[OW + 2 * KHALF + 6];
    __shared__ float warp_sums[THREADS / 32];

    const int t = threadIdx.x;
    const int strip = blockIdx.x;
    const int b = blockIdx.y;
    const int r0 = strip * ROWS_PER_STRIP;

    const float* base1 = img1 + (size_t)b * 3 * IMG_H * IMG_W;
    const float* base2 = img2 + (size_t)b * 3 * IMG_H * IMG_W;

    const bool active = (t < NCOLT);
    const int c = 2 * t;

    float h[5][11][2];
    float vs[5][2];
    #pragma unroll
    for (int q = 0; q < 5; q++) { vs[q][0] = 0.0f; vs[q][1] = 0.0f; }

    float acc = 0.0f;

    // Warmup: ingest cropped rows r0-5 .. r0+4 into slots 0..9
    #pragma unroll
    for (int w = 0; w < 2 * KHALF; w++) {
        ingest_row(base1, base2, r0 - KHALF + w, c, active, h, vs, s1, s2, t, w);
    }

    // Main loop: output rows r0 .. r0+55. Outer base stays a multiple of 11 so
    // all ring indices are compile-time constants after the inner unroll.
    for (int base = 0; base < ROWS_PER_STRIP; base += 11) {
        #pragma unroll
        for (int kk = 0; kk < 11; kk++) {
            int k = base + kk;
            if (k >= ROWS_PER_STRIP) break;
            // ingest input row (r0+k+5) into slot (kk+10)%11 -> window complete
            ingest_row(base1, base2, r0 + k + KHALF, c, active, h, vs, s1, s2, t,
                       (kk + 10) % 11);
            if (active) {
                acc += ssim_val(vs[0][0], vs[1][0], vs[2][0], vs[3][0], vs[4][0]);
                acc += ssim_val(vs[0][1], vs[1][1], vs[2][1], vs[3][1], vs[4][1]);
            }
            // remove the row leaving the window (was ingested at slot kk%11)
            #pragma unroll
            for (int q = 0; q < 5; q++) {
                vs[q][0] -= h[q][kk % 11][0];
                vs[q][1] -= h[q][kk % 11][1];
            }
        }
    }

    // Reduction: warp shuffle -> smem -> atomicAdd(double)
    #pragma unroll
    for (int off = 16; off > 0; off >>= 1)
        acc += __shfl_down_sync(0xFFFFFFFFu, acc, off);
    if ((t & 31) == 0) warp_sums[t >> 5] = acc;
    __syncthreads();
    if (t == 0) {
        float s = 0.0f;
        #pragma unroll
        for (int w = 0; w < THREADS / 32; w++) s += warp_sums[w];
        atomicAdd(&g_ssim_acc, (double)s);
    }
}

extern "C" void kernel_launch(void* const* d_in, const int* in_sizes, int n_in,
                              void* d_out, int out_size)
{
    const float* img1 = (const float*)d_in[0];
    const float* img2 = (const float*)d_in[1];
    float* out = (float*)d_out;

    ssim_init_kernel<<<1, 1>>>();
    dim3 grid(NSTRIPS, NB);
    ssim_main_kernel<<<grid, THREADS>>>(img1, img2);
    ssim_final_kernel<<<1, 1>>>(out);
}

// round 5
// speedup vs baseline: 1.3582x; 1.3582x over previous
#include <cuda_runtime.h>

// Fused SSIM for GB300 (sm_103a). Single kernel launch.
// img1, img2 : (16, 3, 512, 512) fp32; channel 0, crop [4:508) -> 504x504,
// 11x11 zero-padded box filters, SSIM map, global mean -> 1 fp32 scalar.

#define IMG_H 512
#define IMG_W 512
#define CROP 4
#define OH 504
#define OW 504
#define NB 16
#define KS 11
#define KHALF 5

#define ROWS_PER_STRIP 56
#define NSTRIPS 9              // 9 * 56 = 504
#define THREADS 256
#define NCOLT 252              // threads 0..251 own 2 output columns each
#define NBLOCKS (NSTRIPS * NB) // 144 blocks -> 1/SM, single wave
#define SROW 516               // 514 used + pad (16B-aligned buffers)

__device__ double g_acc;          // zero-init at module load; self-resetting
__device__ unsigned int g_count;

struct Pref { float a0, a1, b0, b1; };

// Prefetch one input row's staged elements into registers.
// smem index j maps to cropped col (j-5); valid j in [5,509); global col j-1.
// Thread t owns j = t and j = t+256. j in {512,513} is constant zero.
__device__ __forceinline__ Pref prefetch_row(const float* __restrict__ base1,
                                             const float* __restrict__ base2,
                                             int irow, int t)
{
    Pref p; p.a0 = p.a1 = p.b0 = p.b1 = 0.0f;
    if (irow >= 0 && irow < OH) {
        const float* r1 = base1 + (size_t)(irow + CROP) * IMG_W;
        const float* r2 = base2 + (size_t)(irow + CROP) * IMG_W;
        if (t >= KHALF) { p.a0 = r1[t - 1];   p.b0 = r2[t - 1]; }
        if (t < 253)    { p.a1 = r1[t + 255]; p.b1 = r2[t + 255]; }
    }
    return p;
}

// Horizontal 11-wide window sums for 2 adjacent columns (c even).
// o = {ha0,ha1, hb0,hb1, haa0,haa1, hbb0,hbb1, hab0,hab1}
__device__ __forceinline__ void hsums(const float* __restrict__ p1,
                                      const float* __restrict__ p2,
                                      float o[10])
{
    float a[12], b[12];
    const float2* q1 = reinterpret_cast<const float2*>(p1);
    const float2* q2 = reinterpret_cast<const float2*>(p2);
    #pragma unroll
    for (int i = 0; i < 6; i++) {
        float2 va = q1[i], vb = q2[i];
        a[2*i] = va.x; a[2*i+1] = va.y;
        b[2*i] = vb.x; b[2*i+1] = vb.y;
    }
    float ha = 0.f, hb = 0.f, haa = 0.f, hbb = 0.f, hab = 0.f;
    #pragma unroll
    for (int j = 0; j < KS; j++) {
        ha += a[j];
        hb += b[j];
        haa = fmaf(a[j], a[j], haa);
        hbb = fmaf(b[j], b[j], hbb);
        hab = fmaf(a[j], b[j], hab);
    }
    o[0] = ha;  o[1] = ha - a[0] + a[11];
    o[2] = hb;  o[3] = hb - b[0] + b[11];
    o[4] = haa; o[5] = fmaf(a[11], a[11], fmaf(a[0], -a[0], haa));
    o[6] = hbb; o[7] = fmaf(b[11], b[11], fmaf(b[0], -b[0], hbb));
    o[8] = hab; o[9] = fmaf(a[11], b[11], fmaf(a[0], -b[0], hab));
}

__device__ __forceinline__ float ssim_val(float S1, float S2, float Saa,
                                          float Sbb, float Sab)
{
    const float inv = 1.0f / 121.0f;
    const float C1 = 6.5025f;    // (0.01*255)^2
    const float C2 = 58.5225f;   // (0.03*255)^2
    float m1 = S1 * inv;
    float m2 = S2 * inv;
    float m11 = m1 * m1;
    float m22 = m2 * m2;
    float m12 = m1 * m2;
    float s11 = fmaf(Saa, inv, -m11);
    float s22 = fmaf(Sbb, inv, -m22);
    float s12 = fmaf(Sab, inv, -m12);
    float num = fmaf(2.0f, m12, C1) * fmaf(2.0f, s12, C2);
    float den = (m11 + m22 + C1) * (s11 + s22 + C2);
    return __fdividef(num, den);
}

__global__ __launch_bounds__(THREADS, 1)
void ssim_main(const float* __restrict__ img1,
               const float* __restrict__ img2,
               float* __restrict__ out)
{
    __shared__ __align__(16) float sm1[2][SROW];
    __shared__ __align__(16) float sm2[2][SROW];
    __shared__ float warp_sums[THREADS / 32];

    const int t = threadIdx.x;
    const int strip = blockIdx.x;
    const int b = blockIdx.y;
    const int r0 = strip * ROWS_PER_STRIP;

    const float* base1 = img1 + (size_t)b * 3 * IMG_H * IMG_W;
    const float* base2 = img2 + (size_t)b * 3 * IMG_H * IMG_W;

    const bool active = (t < NCOLT);
    const int c = 2 * t;

    // constant-zero tail slots (never re-stored)
    if (t < 2) {
        sm1[0][512 + t] = 0.f; sm1[1][512 + t] = 0.f;
        sm2[0][512 + t] = 0.f; sm2[1][512 + t] = 0.f;
    }

    float h[5][11][2];   // horizontal-sum ring, 11 rows deep, 2 cols
    float vs[5][2];      // vertical running sums over the 11-row window
    #pragma unroll
    for (int q = 0; q < 5; q++) { vs[q][0] = 0.f; vs[q][1] = 0.f; }

    float acc = 0.0f;
    int par = 0;

    // Pipeline prologue: prefetch first ingested row (cropped row r0-5).
    Pref p = prefetch_row(base1, base2, r0 - KHALF, t);

    // Warmup: ingest cropped rows r0-5 .. r0+4 into ring slots 0..9.
    #pragma unroll
    for (int w = 0; w < 2 * KHALF; w++) {
        sm1[par][t] = p.a0; sm1[par][t + 256] = p.a1;
        sm2[par][t] = p.b0; sm2[par][t + 256] = p.b1;
        p = prefetch_row(base1, base2, r0 - KHALF + w + 1, t);  // LDGs in flight
        __syncthreads();
        if (active) {
            float o[10];
            hsums(&sm1[par][c], &sm2[par][c], o);
            #pragma unroll
            for (int q = 0; q < 5; q++) {
                h[q][w][0] = o[2*q];   vs[q][0] += o[2*q];
                h[q][w][1] = o[2*q+1]; vs[q][1] += o[2*q+1];
            }
        }
        par ^= 1;
    }

    // Main loop: 56 output rows. Inner unroll of 11 keeps ring slots
    // compile-time so the ring stays in registers.
    for (int bs = 0; bs < ROWS_PER_STRIP; bs += 11) {
        #pragma unroll
        for (int kk = 0; kk < 11; kk++) {
            int k = bs + kk;
            if (k >= ROWS_PER_STRIP) break;
            // stage prefetched input row (r0+k+5) -> window complete
            sm1[par][t] = p.a0; sm1[par][t + 256] = p.a1;
            sm2[par][t] = p.b0; sm2[par][t + 256] = p.b1;
            p = prefetch_row(base1, base2, r0 + k + KHALF + 1, t);
            __syncthreads();
            if (active) {
                float o[10];
                hsums(&sm1[par][c], &sm2[par][c], o);
                const int sn = (kk + 10) % 11;   // slot entering
                const int so = kk % 11;          // slot leaving (next window)
                #pragma unroll
                for (int q = 0; q < 5; q++) {
                    h[q][sn][0] = o[2*q];   vs[q][0] += o[2*q];
                    h[q][sn][1] = o[2*q+1]; vs[q][1] += o[2*q+1];
                }
                acc += ssim_val(vs[0][0], vs[1][0], vs[2][0], vs[3][0], vs[4][0]);
                acc += ssim_val(vs[0][1], vs[1][1], vs[2][1], vs[3][1], vs[4][1]);
                #pragma unroll
                for (int q = 0; q < 5; q++) {
                    vs[q][0] -= h[q][so][0];
                    vs[q][1] -= h[q][so][1];
                }
            }
            par ^= 1;
        }
    }

    // Block reduction: warp shuffle -> smem -> one atomicAdd(double) per block.
    #pragma unroll
    for (int off = 16; off > 0; off >>= 1)
        acc += __shfl_down_sync(0xFFFFFFFFu, acc, off);
    if ((t & 31) == 0) warp_sums[t >> 5] = acc;
    __syncthreads();

    if (t == 0) {
        float s = 0.0f;
        #pragma unroll
        for (int w = 0; w < THREADS / 32; w++) s += warp_sums[w];
        atomicAdd(&g_acc, (double)s);
        __threadfence();
        unsigned int cnt = atomicAdd(&g_count, 1u);
        if (cnt == (unsigned int)(NBLOCKS - 1)) {
            // All blocks' g_acc adds are visible (fence-before-count ordering).
            double v = atomicAdd(&g_acc, 0.0);
            out[0] = (float)(v * (1.0 / ((double)NB * OH * OW)));
            // Self-reset so every graph replay starts clean (stream-ordered).
            g_acc = 0.0;
            g_count = 0u;
        }
    }
}

extern "C" void kernel_launch(void* const* d_in, const int* in_sizes, int n_in,
                              void* d_out, int out_size)
{
    const float* img1 = (const float*)d_in[0];
    const float* img2 = (const float*)d_in[1];
    float* out = (float*)d_out;

    dim3 grid(NSTRIPS, NB);
    ssim_main<<<grid, THREADS>>>(img1, img2, out);
}